// round 16
// baseline (speedup 1.0000x reference)
#include <cuda_runtime.h>
#include <cuda_bf16.h>
#include <math_constants.h>
#include <cstdint>

#define IN_DIM 128
#define OUT_DIM 64
#define MAX_N 50000
#define MAX_E 800000
#define ALPHA_LEAKY 0.2f
#define EPS_F 1e-10f

// ---- scratch (device globals; no allocation allowed) ----
__device__ float  g_h[(size_t)MAX_N * OUT_DIM];   // 12.8 MB
__device__ float  g_ssrc[MAX_N];
__device__ float  g_stgt[MAX_N];
__device__ int    g_deg[MAX_N];
__device__ int    g_rowptr[MAX_N + 1];
__device__ int    g_cursor[MAX_N];
__device__ float2 g_pack[MAX_E];                  // (exp(leaky score), src-as-float-bits)

// ---------------------------------------------------------------------------
// histogram of targets
// ---------------------------------------------------------------------------
__global__ void hist_kernel(const int* __restrict__ ei, int E) {
    int i = blockIdx.x * blockDim.x + threadIdx.x;
    if (i >= E) return;
    atomicAdd(&g_deg[__ldg(ei + E + i)], 1);
}

// ---------------------------------------------------------------------------
// fused exclusive scan: ONE block, 1024 threads, 49 contiguous elems/thread.
// Two passes over g_deg (L2-resident, 200KB). Proven correct in R12.
// ---------------------------------------------------------------------------
#define SCAN_ITEMS 49   // ceil(50000 / 1024)

__global__ void __launch_bounds__(1024) scan_all_kernel(int n, int E) {
    __shared__ int wsum[32];
    int t = threadIdx.x;
    int lane = t & 31, w = t >> 5;
    int base = t * SCAN_ITEMS;

    // pass 1: per-thread sum
    int sum = 0;
#pragma unroll
    for (int k = 0; k < SCAN_ITEMS; k++) {
        int idx = base + k;
        if (idx < n) sum += g_deg[idx];
    }

    // block-wide exclusive scan of per-thread sums
    int x = sum;
#pragma unroll
    for (int off = 1; off < 32; off <<= 1) {
        int y = __shfl_up_sync(0xffffffffu, x, off);
        if (lane >= off) x += y;
    }
    if (lane == 31) wsum[w] = x;
    __syncthreads();
    if (w == 0) {
        int s = wsum[lane];
#pragma unroll
        for (int off = 1; off < 32; off <<= 1) {
            int y = __shfl_up_sync(0xffffffffu, s, off);
            if (lane >= off) s += y;
        }
        wsum[lane] = s;
    }
    __syncthreads();
    int run = (x - sum) + ((w > 0) ? wsum[w - 1] : 0);

    // pass 2: write running prefix
#pragma unroll
    for (int k = 0; k < SCAN_ITEMS; k++) {
        int idx = base + k;
        if (idx < n) {
            int v = g_deg[idx];
            g_rowptr[idx] = run;
            g_cursor[idx] = run;
            run += v;
        }
    }
    if (t == 1023) g_rowptr[n] = E;
}

// ---------------------------------------------------------------------------
// GEMM (bf16 split-precision tensor-core) + fused attention partial scores.
// h = (Xhi+Xlo)(Whi+Wlo)^T ~= Xhi*Whi + Xhi*Wlo + Xlo*Whi  (3 bf16 MMAs, fp32 acc)
// Tile: 64 nodes x 64 outs, 256 threads = 8 warps (warp_m 0..3 x warp_n 0..1).
// ---------------------------------------------------------------------------
#define PITCH_BF 136   // 128 + 8 bf16 pad -> 272B row pitch, ldmatrix conflict-free
#define TILE_BF_BYTES (64 * PITCH_BF * 2)
#define GEMM_SMEM_BYTES (4 * TILE_BF_BYTES + 2 * 2 * 64 * 4)

__device__ __forceinline__ uint32_t sm_u32(const void* p) {
    uint32_t a;
    asm("{ .reg .u64 t; cvta.to.shared.u64 t, %1; cvt.u32.u64 %0, t; }"
        : "=r"(a) : "l"(p));
    return a;
}

__device__ __forceinline__ void ldm_x4(uint32_t& r0, uint32_t& r1,
                                       uint32_t& r2, uint32_t& r3, uint32_t addr) {
    asm volatile("ldmatrix.sync.aligned.m8n8.x4.shared.b16 {%0,%1,%2,%3}, [%4];"
                 : "=r"(r0), "=r"(r1), "=r"(r2), "=r"(r3) : "r"(addr));
}

__device__ __forceinline__ void mma_bf16(float& c0, float& c1, float& c2, float& c3,
                                         uint32_t a0, uint32_t a1, uint32_t a2, uint32_t a3,
                                         uint32_t b0, uint32_t b1) {
    asm volatile("mma.sync.aligned.m16n8k16.row.col.f32.bf16.bf16.f32 "
                 "{%0,%1,%2,%3}, {%4,%5,%6,%7}, {%8,%9}, {%0,%1,%2,%3};"
                 : "+f"(c0), "+f"(c1), "+f"(c2), "+f"(c3)
                 : "r"(a0), "r"(a1), "r"(a2), "r"(a3), "r"(b0), "r"(b1));
}

__global__ void __launch_bounds__(256) gemm_kernel(
    const float* __restrict__ X, const float* __restrict__ Wg,
    const float* __restrict__ av, int N)
{
    extern __shared__ char smem[];
    __nv_bfloat16* sXhi = (__nv_bfloat16*)smem;
    __nv_bfloat16* sXlo = (__nv_bfloat16*)(smem + TILE_BF_BYTES);
    __nv_bfloat16* sWhi = (__nv_bfloat16*)(smem + 2 * TILE_BF_BYTES);
    __nv_bfloat16* sWlo = (__nv_bfloat16*)(smem + 3 * TILE_BF_BYTES);
    float* sS = (float*)(smem + 4 * TILE_BF_BYTES);          // [2][64]
    float* sT = sS + 2 * 64;                                  // [2][64]

    int t = threadIdx.x;
    int n0 = blockIdx.x * 64;

    // load + hi/lo split
    for (int idx = t; idx < 64 * 32; idx += 256) {
        int row = idx >> 5;
        int q   = idx & 31;
        int gn  = n0 + row;
        float4 xv = make_float4(0.f, 0.f, 0.f, 0.f);
        if (gn < N) xv = ((const float4*)(X + (size_t)gn * IN_DIM))[q];
        float4 wv = ((const float4*)(Wg + (size_t)row * IN_DIM))[q];

        float xf[4] = {xv.x, xv.y, xv.z, xv.w};
        float wf[4] = {wv.x, wv.y, wv.z, wv.w};
        int boff = row * PITCH_BF + q * 4;
#pragma unroll
        for (int c = 0; c < 4; c++) {
            __nv_bfloat16 xh = __float2bfloat16(xf[c]);
            __nv_bfloat16 xl = __float2bfloat16(xf[c] - __bfloat162float(xh));
            __nv_bfloat16 wh = __float2bfloat16(wf[c]);
            __nv_bfloat16 wl = __float2bfloat16(wf[c] - __bfloat162float(wh));
            sXhi[boff + c] = xh;  sXlo[boff + c] = xl;
            sWhi[boff + c] = wh;  sWlo[boff + c] = wl;
        }
    }
    __syncthreads();

    int lane   = t & 31;
    int warp   = t >> 5;
    int warp_m = warp >> 1;
    int warp_n = warp & 1;

    int aRow = warp_m * 16 + (lane & 15);
    int aCol = (lane >> 4) * 8;
    uint32_t aHi = sm_u32(sXhi + aRow * PITCH_BF + aCol);
    uint32_t aLo = sm_u32(sXlo + aRow * PITCH_BF + aCol);

    int bRow0 = warp_n * 32 + (lane & 7) + ((lane >> 4) & 1) * 8;
    int bRow1 = bRow0 + 16;
    int bCol  = ((lane >> 3) & 1) * 8;
    uint32_t bHi0 = sm_u32(sWhi + bRow0 * PITCH_BF + bCol);
    uint32_t bHi1 = sm_u32(sWhi + bRow1 * PITCH_BF + bCol);
    uint32_t bLo0 = sm_u32(sWlo + bRow0 * PITCH_BF + bCol);
    uint32_t bLo1 = sm_u32(sWlo + bRow1 * PITCH_BF + bCol);

    float c[4][4];
#pragma unroll
    for (int nf = 0; nf < 4; nf++)
#pragma unroll
        for (int k = 0; k < 4; k++) c[nf][k] = 0.0f;

#pragma unroll
    for (int ks = 0; ks < 8; ks++) {
        uint32_t koff = ks * 32;
        uint32_t ah0, ah1, ah2, ah3, al0, al1, al2, al3;
        ldm_x4(ah0, ah1, ah2, ah3, aHi + koff);
        ldm_x4(al0, al1, al2, al3, aLo + koff);
        uint32_t bh[8], bl[8];
        ldm_x4(bh[0], bh[1], bh[2], bh[3], bHi0 + koff);
        ldm_x4(bh[4], bh[5], bh[6], bh[7], bHi1 + koff);
        ldm_x4(bl[0], bl[1], bl[2], bl[3], bLo0 + koff);
        ldm_x4(bl[4], bl[5], bl[6], bl[7], bLo1 + koff);
#pragma unroll
        for (int nf = 0; nf < 4; nf++) {
            uint32_t b0h = bh[nf * 2], b1h = bh[nf * 2 + 1];
            uint32_t b0l = bl[nf * 2], b1l = bl[nf * 2 + 1];
            mma_bf16(c[nf][0], c[nf][1], c[nf][2], c[nf][3],
                     ah0, ah1, ah2, ah3, b0h, b1h);
            mma_bf16(c[nf][0], c[nf][1], c[nf][2], c[nf][3],
                     ah0, ah1, ah2, ah3, b0l, b1l);
            mma_bf16(c[nf][0], c[nf][1], c[nf][2], c[nf][3],
                     al0, al1, al2, al3, b0h, b1h);
        }
    }

    // write h
    int r0  = warp_m * 16 + (lane >> 2);
    int gn0 = n0 + r0;
#pragma unroll
    for (int nf = 0; nf < 4; nf++) {
        int col = warp_n * 32 + nf * 8 + (lane & 3) * 2;
        if (gn0 < N)
            *(float2*)(g_h + (size_t)gn0 * OUT_DIM + col) = make_float2(c[nf][0], c[nf][1]);
        if (gn0 + 8 < N)
            *(float2*)(g_h + (size_t)(gn0 + 8) * OUT_DIM + col) = make_float2(c[nf][2], c[nf][3]);
    }

    // fused scores
    float ps0 = 0.f, pt0 = 0.f, ps1 = 0.f, pt1 = 0.f;
#pragma unroll
    for (int nf = 0; nf < 4; nf++) {
        int col = warp_n * 32 + nf * 8 + (lane & 3) * 2;
        float a0 = __ldg(av + col),      a1 = __ldg(av + col + 1);
        float b0 = __ldg(av + 64 + col), b1 = __ldg(av + 64 + col + 1);
        ps0 += c[nf][0] * a0 + c[nf][1] * a1;
        pt0 += c[nf][0] * b0 + c[nf][1] * b1;
        ps1 += c[nf][2] * a0 + c[nf][3] * a1;
        pt1 += c[nf][2] * b0 + c[nf][3] * b1;
    }
#pragma unroll
    for (int off = 1; off < 4; off <<= 1) {
        ps0 += __shfl_xor_sync(0xffffffffu, ps0, off);
        pt0 += __shfl_xor_sync(0xffffffffu, pt0, off);
        ps1 += __shfl_xor_sync(0xffffffffu, ps1, off);
        pt1 += __shfl_xor_sync(0xffffffffu, pt1, off);
    }
    if ((lane & 3) == 0) {
        int r = warp_m * 16 + (lane >> 2);
        sS[warp_n * 64 + r]     = ps0;  sT[warp_n * 64 + r]     = pt0;
        sS[warp_n * 64 + r + 8] = ps1;  sT[warp_n * 64 + r + 8] = pt1;
    }
    __syncthreads();
    if (t < 64 && n0 + t < N) {
        g_ssrc[n0 + t] = sS[t] + sS[64 + t];
        g_stgt[n0 + t] = sT[t] + sT[64 + t];
    }
}

// ---------------------------------------------------------------------------
// CSR fill: e = leaky(s_src+s_tgt); store (exp(e), src) at cursor slot.
// ---------------------------------------------------------------------------
__global__ void fill_kernel(const int* __restrict__ ei, int E) {
    int i = blockIdx.x * blockDim.x + threadIdx.x;
    if (i >= E) return;
    int src = __ldg(ei + i);
    int tgt = __ldg(ei + E + i);
    float e = g_ssrc[src] + g_stgt[tgt];
    e = (e > 0.0f) ? e : (ALPHA_LEAKY * e);
    float ex = __expf(e);
    int pos = atomicAdd(&g_cursor[tgt], 1);
    g_pack[pos] = make_float2(ex, __int_as_float(src));
}

// ---------------------------------------------------------------------------
// aggregate: one warp per target, SINGLE pass over its CSR segment.
// ---------------------------------------------------------------------------
__global__ void __launch_bounds__(256) agg_kernel(float* __restrict__ out, int N) {
    int gw   = (blockIdx.x * blockDim.x + threadIdx.x) >> 5;
    int lane = threadIdx.x & 31;
    if (gw >= N) return;

    int beg = g_rowptr[gw];
    int end = g_rowptr[gw + 1];

    float  S   = 0.0f;
    float2 acc = make_float2(0.0f, 0.0f);

    for (int base = beg; base < end; base += 32) {
        int j = base + lane;
        float ex = 0.0f;
        int   src = 0;
        if (j < end) {
            float2 p = __ldg(&g_pack[j]);
            ex  = p.x;
            src = __float_as_int(p.y);
        }
        int cnt = min(32, end - base);
        for (int k = 0; k < cnt; k++) {
            float a  = __shfl_sync(0xffffffffu, ex, k);
            int   sk = __shfl_sync(0xffffffffu, src, k);
            S += a;
            float2 hv = __ldg((const float2*)(g_h + (size_t)sk * OUT_DIM) + lane);
            acc.x = fmaf(a, hv.x, acc.x);
            acc.y = fmaf(a, hv.y, acc.y);
        }
    }

    float inv = 1.0f / (S + EPS_F);
    float2 o;
    o.x = acc.x * inv;
    o.y = acc.y * inv;
    o.x = (o.x > 0.0f) ? o.x : expm1f(o.x);
    o.y = (o.y > 0.0f) ? o.y : expm1f(o.y);
    ((float2*)(out + (size_t)gw * OUT_DIM))[lane] = o;
}

extern "C" void kernel_launch(void* const* d_in, const int* in_sizes, int n_in,
                              void* d_out, int out_size) {
    const float* X   = (const float*)d_in[0];
    const int*   EI  = (const int*)d_in[1];      // int32 edge_index [2, E]
    const float* Wg  = (const float*)d_in[2];
    const float* A   = (const float*)d_in[3];
    float*       out = (float*)d_out;

    int N = in_sizes[0] / IN_DIM;   // 50000
    int E = in_sizes[1] / 2;        // 800000

    // one-time host-side resources (no device memory allocated)
    static cudaStream_t s2 = nullptr;
    static cudaEvent_t  e0 = nullptr, e1 = nullptr;
    static void* deg_ptr = nullptr;
    if (s2 == nullptr) {
        cudaStreamCreateWithFlags(&s2, cudaStreamNonBlocking);
        cudaEventCreateWithFlags(&e0, cudaEventDisableTiming);
        cudaEventCreateWithFlags(&e1, cudaEventDisableTiming);
        cudaGetSymbolAddress(&deg_ptr, g_deg);
        cudaFuncSetAttribute(gemm_kernel,
                             cudaFuncAttributeMaxDynamicSharedMemorySize,
                             GEMM_SMEM_BYTES);
    }

    // fork CSR-build chain onto side stream (overlaps with GEMM)
    cudaEventRecord(e0, (cudaStream_t)0);
    cudaStreamWaitEvent(s2, e0, 0);
    cudaMemsetAsync(deg_ptr, 0, (size_t)N * sizeof(int), s2);
    hist_kernel<<<(E + 255) / 256, 256, 0, s2>>>(EI, E);
    scan_all_kernel<<<1, 1024, 0, s2>>>(N, E);
    cudaEventRecord(e1, s2);

    // main chain: GEMM (+fused scores) on capture stream
    gemm_kernel<<<(N + 63) / 64, 256, GEMM_SMEM_BYTES>>>(X, Wg, A, N);

    // join: fill needs scores (main) + cursor/rowptr (side)
    cudaStreamWaitEvent((cudaStream_t)0, e1, 0);
    fill_kernel<<<(E + 255) / 256, 256>>>(EI, E);
    agg_kernel<<<(unsigned)(((size_t)N * 32 + 255) / 256), 256>>>(out, N);
}

// round 17
// speedup vs baseline: 4.4500x; 4.4500x over previous
#include <cuda_runtime.h>
#include <cuda_bf16.h>
#include <math_constants.h>
#include <cstdint>

#define IN_DIM 128
#define OUT_DIM 64
#define MAX_N 50000
#define MAX_E 800000
#define ALPHA_LEAKY 0.2f
#define EPS_F 1e-10f

#define SCAN_CHUNK 1024

// ---- scratch (device globals; no allocation allowed) ----
__device__ float  g_h[(size_t)MAX_N * OUT_DIM];   // 12.8 MB
__device__ float  g_ssrc[MAX_N];
__device__ float  g_stgt[MAX_N];
__device__ int    g_deg[MAX_N];
__device__ int    g_rowptr[MAX_N + 1];
__device__ int    g_cursor[MAX_N];
__device__ int    g_bsum[(MAX_N + SCAN_CHUNK - 1) / SCAN_CHUNK];
__device__ float2 g_pack[MAX_E];                  // (exp(leaky score), src-as-float-bits)

// ---------------------------------------------------------------------------
// histogram of targets
// ---------------------------------------------------------------------------
__global__ void hist_kernel(const int* __restrict__ ei, int E) {
    int i = blockIdx.x * blockDim.x + threadIdx.x;
    if (i >= E) return;
    atomicAdd(&g_deg[__ldg(ei + E + i)], 1);
}

// ---------------------------------------------------------------------------
// exclusive scan, 3 phases (chunk=1024)  [side stream, hidden under GEMM]
// NOTE: do NOT replace with a single-block fused scan — both configs that
// used one (R12, R16) regressed catastrophically (210/286us).
// ---------------------------------------------------------------------------
__global__ void __launch_bounds__(SCAN_CHUNK) scan1_kernel(int n) {
    __shared__ int wsum[32];
    int t = threadIdx.x, b = blockIdx.x;
    int gi = b * SCAN_CHUNK + t;
    int lane = t & 31, w = t >> 5;
    int v = (gi < n) ? g_deg[gi] : 0;
    int x = v;
#pragma unroll
    for (int off = 1; off < 32; off <<= 1) {
        int y = __shfl_up_sync(0xffffffffu, x, off);
        if (lane >= off) x += y;
    }
    if (lane == 31) wsum[w] = x;
    __syncthreads();
    if (w == 0) {
        int s = wsum[lane];
#pragma unroll
        for (int off = 1; off < 32; off <<= 1) {
            int y = __shfl_up_sync(0xffffffffu, s, off);
            if (lane >= off) s += y;
        }
        wsum[lane] = s;
    }
    __syncthreads();
    int incl = x + ((w > 0) ? wsum[w - 1] : 0);
    if (gi < n) g_rowptr[gi] = incl - v;
    if (t == SCAN_CHUNK - 1) g_bsum[b] = incl;
}

__global__ void __launch_bounds__(SCAN_CHUNK) scan2_kernel(int nb) {
    __shared__ int wsum[32];
    int t = threadIdx.x;
    int lane = t & 31, w = t >> 5;
    int v = (t < nb) ? g_bsum[t] : 0;
    int x = v;
#pragma unroll
    for (int off = 1; off < 32; off <<= 1) {
        int y = __shfl_up_sync(0xffffffffu, x, off);
        if (lane >= off) x += y;
    }
    if (lane == 31) wsum[w] = x;
    __syncthreads();
    if (w == 0) {
        int s = wsum[lane];
#pragma unroll
        for (int off = 1; off < 32; off <<= 1) {
            int y = __shfl_up_sync(0xffffffffu, s, off);
            if (lane >= off) s += y;
        }
        wsum[lane] = s;
    }
    __syncthreads();
    int incl = x + ((w > 0) ? wsum[w - 1] : 0);
    if (t < nb) g_bsum[t] = incl - v;
}

__global__ void scan3_kernel(int n, int E) {
    int gi = blockIdx.x * blockDim.x + threadIdx.x;
    if (gi < n) {
        int r = g_rowptr[gi] + g_bsum[gi >> 10];
        g_rowptr[gi] = r;
        g_cursor[gi] = r;
    }
    if (gi == 0) g_rowptr[n] = E;
}

// ---------------------------------------------------------------------------
// GEMM (bf16 split-precision tensor-core) + fused attention partial scores.
// h = (Xhi+Xlo)(Whi+Wlo)^T ~= Xhi*Whi + Xhi*Wlo + Xlo*Whi  (3 bf16 MMAs, fp32 acc)
// ---------------------------------------------------------------------------
#define PITCH_BF 136
#define TILE_BF_BYTES (64 * PITCH_BF * 2)
#define GEMM_SMEM_BYTES (4 * TILE_BF_BYTES + 2 * 2 * 64 * 4)

__device__ __forceinline__ uint32_t sm_u32(const void* p) {
    uint32_t a;
    asm("{ .reg .u64 t; cvta.to.shared.u64 t, %1; cvt.u32.u64 %0, t; }"
        : "=r"(a) : "l"(p));
    return a;
}

__device__ __forceinline__ void ldm_x4(uint32_t& r0, uint32_t& r1,
                                       uint32_t& r2, uint32_t& r3, uint32_t addr) {
    asm volatile("ldmatrix.sync.aligned.m8n8.x4.shared.b16 {%0,%1,%2,%3}, [%4];"
                 : "=r"(r0), "=r"(r1), "=r"(r2), "=r"(r3) : "r"(addr));
}

__device__ __forceinline__ void mma_bf16(float& c0, float& c1, float& c2, float& c3,
                                         uint32_t a0, uint32_t a1, uint32_t a2, uint32_t a3,
                                         uint32_t b0, uint32_t b1) {
    asm volatile("mma.sync.aligned.m16n8k16.row.col.f32.bf16.bf16.f32 "
                 "{%0,%1,%2,%3}, {%4,%5,%6,%7}, {%8,%9}, {%0,%1,%2,%3};"
                 : "+f"(c0), "+f"(c1), "+f"(c2), "+f"(c3)
                 : "r"(a0), "r"(a1), "r"(a2), "r"(a3), "r"(b0), "r"(b1));
}

__global__ void __launch_bounds__(256) gemm_kernel(
    const float* __restrict__ X, const float* __restrict__ Wg,
    const float* __restrict__ av, int N)
{
    extern __shared__ char smem[];
    __nv_bfloat16* sXhi = (__nv_bfloat16*)smem;
    __nv_bfloat16* sXlo = (__nv_bfloat16*)(smem + TILE_BF_BYTES);
    __nv_bfloat16* sWhi = (__nv_bfloat16*)(smem + 2 * TILE_BF_BYTES);
    __nv_bfloat16* sWlo = (__nv_bfloat16*)(smem + 3 * TILE_BF_BYTES);
    float* sS = (float*)(smem + 4 * TILE_BF_BYTES);
    float* sT = sS + 2 * 64;

    int t = threadIdx.x;
    int n0 = blockIdx.x * 64;

    for (int idx = t; idx < 64 * 32; idx += 256) {
        int row = idx >> 5;
        int q   = idx & 31;
        int gn  = n0 + row;
        float4 xv = make_float4(0.f, 0.f, 0.f, 0.f);
        if (gn < N) xv = ((const float4*)(X + (size_t)gn * IN_DIM))[q];
        float4 wv = ((const float4*)(Wg + (size_t)row * IN_DIM))[q];

        float xf[4] = {xv.x, xv.y, xv.z, xv.w};
        float wf[4] = {wv.x, wv.y, wv.z, wv.w};
        int boff = row * PITCH_BF + q * 4;
#pragma unroll
        for (int c = 0; c < 4; c++) {
            __nv_bfloat16 xh = __float2bfloat16(xf[c]);
            __nv_bfloat16 xl = __float2bfloat16(xf[c] - __bfloat162float(xh));
            __nv_bfloat16 wh = __float2bfloat16(wf[c]);
            __nv_bfloat16 wl = __float2bfloat16(wf[c] - __bfloat162float(wh));
            sXhi[boff + c] = xh;  sXlo[boff + c] = xl;
            sWhi[boff + c] = wh;  sWlo[boff + c] = wl;
        }
    }
    __syncthreads();

    int lane   = t & 31;
    int warp   = t >> 5;
    int warp_m = warp >> 1;
    int warp_n = warp & 1;

    int aRow = warp_m * 16 + (lane & 15);
    int aCol = (lane >> 4) * 8;
    uint32_t aHi = sm_u32(sXhi + aRow * PITCH_BF + aCol);
    uint32_t aLo = sm_u32(sXlo + aRow * PITCH_BF + aCol);

    int bRow0 = warp_n * 32 + (lane & 7) + ((lane >> 4) & 1) * 8;
    int bRow1 = bRow0 + 16;
    int bCol  = ((lane >> 3) & 1) * 8;
    uint32_t bHi0 = sm_u32(sWhi + bRow0 * PITCH_BF + bCol);
    uint32_t bHi1 = sm_u32(sWhi + bRow1 * PITCH_BF + bCol);
    uint32_t bLo0 = sm_u32(sWlo + bRow0 * PITCH_BF + bCol);
    uint32_t bLo1 = sm_u32(sWlo + bRow1 * PITCH_BF + bCol);

    float c[4][4];
#pragma unroll
    for (int nf = 0; nf < 4; nf++)
#pragma unroll
        for (int k = 0; k < 4; k++) c[nf][k] = 0.0f;

#pragma unroll
    for (int ks = 0; ks < 8; ks++) {
        uint32_t koff = ks * 32;
        uint32_t ah0, ah1, ah2, ah3, al0, al1, al2, al3;
        ldm_x4(ah0, ah1, ah2, ah3, aHi + koff);
        ldm_x4(al0, al1, al2, al3, aLo + koff);
        uint32_t bh[8], bl[8];
        ldm_x4(bh[0], bh[1], bh[2], bh[3], bHi0 + koff);
        ldm_x4(bh[4], bh[5], bh[6], bh[7], bHi1 + koff);
        ldm_x4(bl[0], bl[1], bl[2], bl[3], bLo0 + koff);
        ldm_x4(bl[4], bl[5], bl[6], bl[7], bLo1 + koff);
#pragma unroll
        for (int nf = 0; nf < 4; nf++) {
            uint32_t b0h = bh[nf * 2], b1h = bh[nf * 2 + 1];
            uint32_t b0l = bl[nf * 2], b1l = bl[nf * 2 + 1];
            mma_bf16(c[nf][0], c[nf][1], c[nf][2], c[nf][3],
                     ah0, ah1, ah2, ah3, b0h, b1h);
            mma_bf16(c[nf][0], c[nf][1], c[nf][2], c[nf][3],
                     ah0, ah1, ah2, ah3, b0l, b1l);
            mma_bf16(c[nf][0], c[nf][1], c[nf][2], c[nf][3],
                     al0, al1, al2, al3, b0h, b1h);
        }
    }

    int r0  = warp_m * 16 + (lane >> 2);
    int gn0 = n0 + r0;
#pragma unroll
    for (int nf = 0; nf < 4; nf++) {
        int col = warp_n * 32 + nf * 8 + (lane & 3) * 2;
        if (gn0 < N)
            *(float2*)(g_h + (size_t)gn0 * OUT_DIM + col) = make_float2(c[nf][0], c[nf][1]);
        if (gn0 + 8 < N)
            *(float2*)(g_h + (size_t)(gn0 + 8) * OUT_DIM + col) = make_float2(c[nf][2], c[nf][3]);
    }

    float ps0 = 0.f, pt0 = 0.f, ps1 = 0.f, pt1 = 0.f;
#pragma unroll
    for (int nf = 0; nf < 4; nf++) {
        int col = warp_n * 32 + nf * 8 + (lane & 3) * 2;
        float a0 = __ldg(av + col),      a1 = __ldg(av + col + 1);
        float b0 = __ldg(av + 64 + col), b1 = __ldg(av + 64 + col + 1);
        ps0 += c[nf][0] * a0 + c[nf][1] * a1;
        pt0 += c[nf][0] * b0 + c[nf][1] * b1;
        ps1 += c[nf][2] * a0 + c[nf][3] * a1;
        pt1 += c[nf][2] * b0 + c[nf][3] * b1;
    }
#pragma unroll
    for (int off = 1; off < 4; off <<= 1) {
        ps0 += __shfl_xor_sync(0xffffffffu, ps0, off);
        pt0 += __shfl_xor_sync(0xffffffffu, pt0, off);
        ps1 += __shfl_xor_sync(0xffffffffu, ps1, off);
        pt1 += __shfl_xor_sync(0xffffffffu, pt1, off);
    }
    if ((lane & 3) == 0) {
        int r = warp_m * 16 + (lane >> 2);
        sS[warp_n * 64 + r]     = ps0;  sT[warp_n * 64 + r]     = pt0;
        sS[warp_n * 64 + r + 8] = ps1;  sT[warp_n * 64 + r + 8] = pt1;
    }
    __syncthreads();
    if (t < 64 && n0 + t < N) {
        g_ssrc[n0 + t] = sS[t] + sS[64 + t];
        g_stgt[n0 + t] = sT[t] + sT[64 + t];
    }
}

// ---------------------------------------------------------------------------
// CSR fill: e = leaky(s_src+s_tgt); store (exp(e), src) at cursor slot.
// ---------------------------------------------------------------------------
__global__ void fill_kernel(const int* __restrict__ ei, int E) {
    int i = blockIdx.x * blockDim.x + threadIdx.x;
    if (i >= E) return;
    int src = __ldg(ei + i);
    int tgt = __ldg(ei + E + i);
    float e = g_ssrc[src] + g_stgt[tgt];
    e = (e > 0.0f) ? e : (ALPHA_LEAKY * e);
    float ex = __expf(e);
    int pos = atomicAdd(&g_cursor[tgt], 1);
    g_pack[pos] = make_float2(ex, __int_as_float(src));
}

// ---------------------------------------------------------------------------
// aggregate: one warp per target, single pass; broadcast loop unrolled x4
// so four independent 256B h-gathers are in flight per step.
// ---------------------------------------------------------------------------
__global__ void __launch_bounds__(256) agg_kernel(float* __restrict__ out, int N) {
    int gw   = (blockIdx.x * blockDim.x + threadIdx.x) >> 5;
    int lane = threadIdx.x & 31;
    if (gw >= N) return;

    int beg = g_rowptr[gw];
    int end = g_rowptr[gw + 1];

    float  S   = 0.0f;
    float2 acc = make_float2(0.0f, 0.0f);

    for (int base = beg; base < end; base += 32) {
        int j = base + lane;
        float ex = 0.0f;
        int   src = 0;
        if (j < end) {
            float2 p = __ldg(&g_pack[j]);
            ex  = p.x;
            src = __float_as_int(p.y);
        }
        int cnt = min(32, end - base);
        int k = 0;
        for (; k + 4 <= cnt; k += 4) {
            float a0 = __shfl_sync(0xffffffffu, ex, k);
            float a1 = __shfl_sync(0xffffffffu, ex, k + 1);
            float a2 = __shfl_sync(0xffffffffu, ex, k + 2);
            float a3 = __shfl_sync(0xffffffffu, ex, k + 3);
            int   s0 = __shfl_sync(0xffffffffu, src, k);
            int   s1 = __shfl_sync(0xffffffffu, src, k + 1);
            int   s2 = __shfl_sync(0xffffffffu, src, k + 2);
            int   s3 = __shfl_sync(0xffffffffu, src, k + 3);
            float2 h0 = __ldg((const float2*)(g_h + (size_t)s0 * OUT_DIM) + lane);
            float2 h1 = __ldg((const float2*)(g_h + (size_t)s1 * OUT_DIM) + lane);
            float2 h2 = __ldg((const float2*)(g_h + (size_t)s2 * OUT_DIM) + lane);
            float2 h3 = __ldg((const float2*)(g_h + (size_t)s3 * OUT_DIM) + lane);
            S += (a0 + a1) + (a2 + a3);
            acc.x = fmaf(a0, h0.x, acc.x);  acc.y = fmaf(a0, h0.y, acc.y);
            acc.x = fmaf(a1, h1.x, acc.x);  acc.y = fmaf(a1, h1.y, acc.y);
            acc.x = fmaf(a2, h2.x, acc.x);  acc.y = fmaf(a2, h2.y, acc.y);
            acc.x = fmaf(a3, h3.x, acc.x);  acc.y = fmaf(a3, h3.y, acc.y);
        }
        for (; k < cnt; k++) {
            float a  = __shfl_sync(0xffffffffu, ex, k);
            int   sk = __shfl_sync(0xffffffffu, src, k);
            S += a;
            float2 hv = __ldg((const float2*)(g_h + (size_t)sk * OUT_DIM) + lane);
            acc.x = fmaf(a, hv.x, acc.x);
            acc.y = fmaf(a, hv.y, acc.y);
        }
    }

    float inv = 1.0f / (S + EPS_F);
    float2 o;
    o.x = acc.x * inv;
    o.y = acc.y * inv;
    o.x = (o.x > 0.0f) ? o.x : expm1f(o.x);
    o.y = (o.y > 0.0f) ? o.y : expm1f(o.y);
    ((float2*)(out + (size_t)gw * OUT_DIM))[lane] = o;
}

extern "C" void kernel_launch(void* const* d_in, const int* in_sizes, int n_in,
                              void* d_out, int out_size) {
    const float* X   = (const float*)d_in[0];
    const int*   EI  = (const int*)d_in[1];      // int32 edge_index [2, E]
    const float* Wg  = (const float*)d_in[2];
    const float* A   = (const float*)d_in[3];
    float*       out = (float*)d_out;

    int N = in_sizes[0] / IN_DIM;   // 50000
    int E = in_sizes[1] / 2;        // 800000
    int nb = (N + SCAN_CHUNK - 1) / SCAN_CHUNK;

    // one-time host-side resources (no device memory allocated)
    static cudaStream_t s2 = nullptr;
    static cudaEvent_t  e0 = nullptr, e1 = nullptr;
    static void* deg_ptr = nullptr;
    if (s2 == nullptr) {
        cudaStreamCreateWithFlags(&s2, cudaStreamNonBlocking);
        cudaEventCreateWithFlags(&e0, cudaEventDisableTiming);
        cudaEventCreateWithFlags(&e1, cudaEventDisableTiming);
        cudaGetSymbolAddress(&deg_ptr, g_deg);
        cudaFuncSetAttribute(gemm_kernel,
                             cudaFuncAttributeMaxDynamicSharedMemorySize,
                             GEMM_SMEM_BYTES);
    }

    // fork CSR-build chain onto side stream (overlaps with GEMM)
    cudaEventRecord(e0, (cudaStream_t)0);
    cudaStreamWaitEvent(s2, e0, 0);
    cudaMemsetAsync(deg_ptr, 0, (size_t)N * sizeof(int), s2);
    hist_kernel<<<(E + 255) / 256, 256, 0, s2>>>(EI, E);
    scan1_kernel<<<nb, SCAN_CHUNK, 0, s2>>>(N);
    scan2_kernel<<<1, SCAN_CHUNK, 0, s2>>>(nb);
    scan3_kernel<<<(N + 255) / 256, 256, 0, s2>>>(N, E);
    cudaEventRecord(e1, s2);

    // main chain: GEMM (+fused scores) on capture stream
    gemm_kernel<<<(N + 63) / 64, 256, GEMM_SMEM_BYTES>>>(X, Wg, A, N);

    // join: fill needs scores (main) + cursor/rowptr (side)
    cudaStreamWaitEvent((cudaStream_t)0, e1, 0);
    fill_kernel<<<(E + 255) / 256, 256>>>(EI, E);
    agg_kernel<<<(unsigned)(((size_t)N * 32 + 255) / 256), 256>>>(out, N);
}